// round 2
// baseline (speedup 1.0000x reference)
#include <cuda_runtime.h>
#include <cstdint>

// Problem constants
#define BB   2
#define LL   2048
#define HH   1024
#define NHH  4
#define KD   512
#define VD   1024
#define DKK  128
#define DVV  256
#define PRR  32
#define GRR  64
#define MT   4096   // total tokens B*L

// ---------------- scratch (static __device__, no allocation) ----------------
__device__ float g_ax[MT * HH];        // lerped x with mu_x
__device__ float g_xp[MT * 160];       // tanh proj, 5*PR
__device__ float g_a0[MT * HH];        // lerped inputs for r
__device__ float g_a1[MT * HH];        // for w
__device__ float g_a2[MT * HH];        // for k
__device__ float g_a3[MT * HH];        // for v
__device__ float g_a4[MT * HH];        // for g
__device__ float g_r [MT * KD];
__device__ float g_k [MT * KD];
__device__ float g_v [MT * VD];
__device__ float g_g [MT * VD];
__device__ float g_wd[MT * GRR];
__device__ float g_ew[MT * KD];        // exp(-exp(w_raw))
__device__ float g_c [MT * NHH];       // bonus scalar per (token, head)
__device__ float g_o [MT * VD];        // recurrence output
__device__ float g_og[MT * VD];        // after LN + gate

// ---------------- elementwise: ax = x + (xprev - x)*mu_x ----------------
__global__ void ax_kernel(const float* __restrict__ x,
                          const float* __restrict__ mu_x,
                          float* __restrict__ ax) {
    size_t i = (size_t)blockIdx.x * blockDim.x + threadIdx.x;
    if (i >= (size_t)MT * HH) return;
    int n = (int)(i & (HH - 1));
    size_t m = i >> 10;
    float mu = mu_x[n];
    float xv = x[i];
    float xp = ((m & (LL - 1)) == 0) ? 0.f : x[i - HH];
    ax[i] = xv + (xp - xv) * mu;
}

// ---------------- generic SGEMM: C = epi(act(A @ W^T + bias)) --------------
// A: [M,K] row-major stride lda. W: [N,K] row-major stride ldw.
// epi: 0 = store, 1 = lerp-with-x (C = x + (xprev-x)*val), 2 = exp(-exp(val))
#define BM 128
#define BN 128
#define BKG 8
__global__ __launch_bounds__(256)
void sgemm_kernel(const float* __restrict__ A, int lda,
                  const float* __restrict__ W, int ldw,
                  float* __restrict__ C, int ldc,
                  int M, int N, int Kdim,
                  const float* __restrict__ bias,
                  int act, int epi,
                  const float* __restrict__ xsrc) {
    __shared__ float As[BKG][BM];
    __shared__ float Bs[BKG][BN];
    int tid = threadIdx.x;
    int mBase = blockIdx.y * BM;
    int nBase = blockIdx.x * BN;
    int lr = tid >> 1;            // 0..127
    int lk = (tid & 1) * 4;       // 0 or 4
    int tx = tid & 15, ty = tid >> 4;
    float acc[8][8];
#pragma unroll
    for (int i = 0; i < 8; i++)
#pragma unroll
        for (int j = 0; j < 8; j++) acc[i][j] = 0.f;

    for (int k0 = 0; k0 < Kdim; k0 += BKG) {
        float4 av = *(const float4*)(A + (size_t)(mBase + lr) * lda + k0 + lk);
        float4 bv = make_float4(0.f, 0.f, 0.f, 0.f);
        if (nBase + lr < N)
            bv = *(const float4*)(W + (size_t)(nBase + lr) * ldw + k0 + lk);
        __syncthreads();
        As[lk + 0][lr] = av.x; As[lk + 1][lr] = av.y;
        As[lk + 2][lr] = av.z; As[lk + 3][lr] = av.w;
        Bs[lk + 0][lr] = bv.x; Bs[lk + 1][lr] = bv.y;
        Bs[lk + 2][lr] = bv.z; Bs[lk + 3][lr] = bv.w;
        __syncthreads();
#pragma unroll
        for (int kk = 0; kk < BKG; kk++) {
            float af[8], bf[8];
#pragma unroll
            for (int i = 0; i < 8; i++) af[i] = As[kk][ty * 8 + i];
#pragma unroll
            for (int j = 0; j < 8; j++) bf[j] = Bs[kk][tx * 8 + j];
#pragma unroll
            for (int i = 0; i < 8; i++)
#pragma unroll
                for (int j = 0; j < 8; j++) acc[i][j] += af[i] * bf[j];
        }
    }
#pragma unroll
    for (int i = 0; i < 8; i++) {
        int m = mBase + ty * 8 + i;
#pragma unroll
        for (int j = 0; j < 8; j++) {
            int n = nBase + tx * 8 + j;
            if (n >= N) continue;
            float v = acc[i][j];
            if (bias) v += bias[n];
            if (act) v = tanhf(v);
            if (epi == 1) {
                float xv = xsrc[(size_t)m * HH + n];
                float xp = ((m & (LL - 1)) == 0) ? 0.f : xsrc[(size_t)(m - 1) * HH + n];
                v = xv + (xp - xv) * v;
            } else if (epi == 2) {
                v = expf(-expf(v));
            }
            C[(size_t)m * ldc + n] = v;
        }
    }
}

// ---------------- per-(token,head) bonus scalar c = sum r*bonus*k ----------
__global__ void c_kernel(const float* __restrict__ r,
                         const float* __restrict__ kk,
                         const float* __restrict__ bonus,
                         float* __restrict__ c) {
    int t = blockIdx.x;
    int h = threadIdx.x >> 5, lane = threadIdx.x & 31;
    const float* rp = r  + (size_t)t * KD + h * DKK;
    const float* kp = kk + (size_t)t * KD + h * DKK;
    const float* bp = bonus + h * DKK;
    float s = 0.f;
#pragma unroll
    for (int j = lane; j < DKK; j += 32) s += rp[j] * bp[j] * kp[j];
#pragma unroll
    for (int o = 16; o; o >>= 1) s += __shfl_xor_sync(0xffffffffu, s, o);
    if (!lane) c[(size_t)t * NHH + h] = s;
}

// ---------------- sequential recurrence (software-pipelined) -------------
// 32 CTAs: 4 per chain (chain = b*NH+h), each CTA covers 64 v-columns.
// Thread layout: kg = tid/64 (32 k each), vi = tid%64. State S[32] in regs.
// Token t+1's operands are prefetched into registers while step t computes
// out of a double-buffered smem tile (hides gmem latency off the chain).
#define OFF_R 0
#define OFF_K 128
#define OFF_W 256
#define OFF_V 384
#define OFF_C 448
__global__ __launch_bounds__(256)
void recur_kernel(const float* __restrict__ r,
                  const float* __restrict__ kk,
                  const float* __restrict__ ew,
                  const float* __restrict__ v,
                  const float* __restrict__ c,
                  float* __restrict__ o) {
    int blk = blockIdx.x;
    int chain = blk >> 2;
    int vb = blk & 3;
    int b = chain >> 2, h = chain & 3;
    int tid = threadIdx.x;
    int kg = tid >> 6;
    int vi = tid & 63;

    __shared__ float buf[2][DKK * 3 + 65];
    __shared__ float part[4][64];

    float S[32];
#pragma unroll
    for (int j = 0; j < 32; j++) S[j] = 0.f;

    size_t tbase = (size_t)b * LL;

    float ar = 0.f, ak = 0.f, aw = 0.f, av = 0.f, ac = 0.f;
    // prologue: load token 0
    {
        size_t tok = tbase;
        if (tid < DKK) {
            ar = r [tok * KD + h * DKK + tid];
            ak = kk[tok * KD + h * DKK + tid];
            aw = ew[tok * KD + h * DKK + tid];
        } else if (tid < DKK + 64) {
            av = v[tok * VD + h * DVV + vb * 64 + (tid - DKK)];
        } else if (tid == DKK + 64) {
            ac = c[tok * NHH + h];
        }
        float* Bn = buf[0];
        if (tid < DKK) {
            Bn[OFF_R + tid] = ar;
            Bn[OFF_K + tid] = ak;
            Bn[OFF_W + tid] = aw;
        } else if (tid < DKK + 64) {
            Bn[OFF_V + (tid - DKK)] = av;
        } else if (tid == DKK + 64) {
            Bn[OFF_C] = ac;
        }
    }
    __syncthreads();

    int pcur = 0;
    for (int t = 0; t < LL; t++) {
        // prefetch token t+1 into registers (overlaps with compute below)
        if (t + 1 < LL) {
            size_t tok = tbase + t + 1;
            if (tid < DKK) {
                ar = r [tok * KD + h * DKK + tid];
                ak = kk[tok * KD + h * DKK + tid];
                aw = ew[tok * KD + h * DKK + tid];
            } else if (tid < DKK + 64) {
                av = v[tok * VD + h * DVV + vb * 64 + (tid - DKK)];
            } else if (tid == DKK + 64) {
                ac = c[tok * NHH + h];
            }
        }

        const float* Bc = buf[pcur];
        // o partial: p = sum_j r[kg*32+j] * S[j]
        float p = 0.f;
#pragma unroll
        for (int j = 0; j < 32; j++) p += Bc[OFF_R + kg * 32 + j] * S[j];
        part[kg][vi] = p;
        __syncthreads();

        if (tid < 64) {
            float cv = Bc[OFF_C];
            float ov = part[0][tid] + part[1][tid] + part[2][tid] + part[3][tid]
                     + cv * Bc[OFF_V + tid];
            o[(tbase + t) * VD + h * DVV + vb * 64 + tid] = ov;
        }
        // state update: S = ew*S + k*v
        float vv = Bc[OFF_V + vi];
#pragma unroll
        for (int j = 0; j < 32; j++) {
            S[j] = Bc[OFF_W + kg * 32 + j] * S[j] + Bc[OFF_K + kg * 32 + j] * vv;
        }

        // stage prefetched token into the other buffer (safe: last reader of
        // that buffer finished at the end-of-previous-iteration barrier)
        if (t + 1 < LL) {
            float* Bn = buf[pcur ^ 1];
            if (tid < DKK) {
                Bn[OFF_R + tid] = ar;
                Bn[OFF_K + tid] = ak;
                Bn[OFF_W + tid] = aw;
            } else if (tid < DKK + 64) {
                Bn[OFF_V + (tid - DKK)] = av;
            } else if (tid == DKK + 64) {
                Bn[OFF_C] = ac;
            }
        }
        __syncthreads();
        pcur ^= 1;
    }
}

// ---------------- per-head LayerNorm + swish gate -----------------------
__global__ __launch_bounds__(256)
void ln_kernel(const float* __restrict__ o,
               const float* __restrict__ g,
               const float* __restrict__ ln_w,
               const float* __restrict__ ln_b,
               float* __restrict__ og) {
    int th = blockIdx.x;
    int t = th >> 2, h = th & 3;
    int vv = threadIdx.x;
    size_t idx = (size_t)t * VD + h * DVV + vv;
    float val = o[idx];

    __shared__ float rs[8], rs2[8];
    float s1 = val, s2 = val * val;
#pragma unroll
    for (int off = 16; off; off >>= 1) {
        s1 += __shfl_xor_sync(0xffffffffu, s1, off);
        s2 += __shfl_xor_sync(0xffffffffu, s2, off);
    }
    int warp = vv >> 5, lane = vv & 31;
    if (!lane) { rs[warp] = s1; rs2[warp] = s2; }
    __syncthreads();
    float tot = 0.f, tot2 = 0.f;
#pragma unroll
    for (int i = 0; i < 8; i++) { tot += rs[i]; tot2 += rs2[i]; }
    float mean = tot * (1.f / DVV);
    float var = tot2 * (1.f / DVV) - mean * mean;
    float inv = rsqrtf(var + 1e-5f);
    float on = (val - mean) * inv * ln_w[vv] + ln_b[vv];
    float gv = g[idx];
    og[idx] = on * gv * (1.f / (1.f + expf(-gv)));
}

// ---------------- host launcher -----------------------------------------
static float* sym(const void* s) {
    void* p = nullptr;
    cudaGetSymbolAddress(&p, s);
    return (float*)p;
}

extern "C" void kernel_launch(void* const* d_in, const int* in_sizes, int n_in,
                              void* d_out, int out_size) {
    const float* x      = (const float*)d_in[0];
    const float* mu_x   = (const float*)d_in[1];
    const float* Wx1    = (const float*)d_in[2];   // [160,1024]
    const float* Wx2    = (const float*)d_in[3];   // [1024,160]
    const float* x_bias = (const float*)d_in[4];   // [5,1024]
    const float* Wr     = (const float*)d_in[5];   // [512,1024]
    const float* Wk     = (const float*)d_in[6];
    const float* Wv     = (const float*)d_in[7];   // [1024,1024]
    const float* Wg     = (const float*)d_in[8];
    const float* Ww1    = (const float*)d_in[9];   // [64,1024]
    const float* Ww2    = (const float*)d_in[10];  // [512,64]
    const float* bw2    = (const float*)d_in[11];  // [512]
    const float* bonus  = (const float*)d_in[12];  // [4,128]
    const float* ln_w   = (const float*)d_in[13];
    const float* ln_b   = (const float*)d_in[14];
    const float* Wo     = (const float*)d_in[15];  // [1024,1024]
    float* out = (float*)d_out;

    float* ax = sym(g_ax); float* xp = sym(g_xp);
    float* a0 = sym(g_a0); float* a1 = sym(g_a1); float* a2 = sym(g_a2);
    float* a3 = sym(g_a3); float* a4 = sym(g_a4);
    float* rb = sym(g_r);  float* kb = sym(g_k);
    float* vb = sym(g_v);  float* gb = sym(g_g);
    float* wd = sym(g_wd); float* ewb = sym(g_ew);
    float* cb = sym(g_c);  float* ob = sym(g_o); float* ogb = sym(g_og);

    dim3 blk256(256);

    // 1. token-shift lerp with mu_x
    ax_kernel<<<(MT * HH + 255) / 256, blk256>>>(x, mu_x, ax);

    // 2. xp = tanh(ax @ Wx1^T)   [4096,160]
    sgemm_kernel<<<dim3(2, 32), blk256>>>(ax, HH, Wx1, HH, xp, 160,
                                          MT, 160, HH, nullptr, 1, 0, nullptr);

    // 3. five mixing GEMMs: a_i = x + (xprev-x) * (xp_i @ Wx2_i^T + bias_i)
    float* aouts[5] = {a0, a1, a2, a3, a4};
    for (int i = 0; i < 5; i++) {
        sgemm_kernel<<<dim3(8, 32), blk256>>>(xp + i * PRR, 160,
                                              Wx2 + i * PRR, 160,
                                              aouts[i], HH,
                                              MT, HH, PRR,
                                              x_bias + i * HH, 0, 1, x);
    }

    // 4. projections
    sgemm_kernel<<<dim3(4, 32), blk256>>>(a0, HH, Wr, HH, rb, KD,
                                          MT, KD, HH, nullptr, 0, 0, nullptr);
    sgemm_kernel<<<dim3(4, 32), blk256>>>(a2, HH, Wk, HH, kb, KD,
                                          MT, KD, HH, nullptr, 0, 0, nullptr);
    sgemm_kernel<<<dim3(8, 32), blk256>>>(a3, HH, Wv, HH, vb, VD,
                                          MT, VD, HH, nullptr, 0, 0, nullptr);
    sgemm_kernel<<<dim3(8, 32), blk256>>>(a4, HH, Wg, HH, gb, VD,
                                          MT, VD, HH, nullptr, 0, 0, nullptr);
    // w LoRA: wd = tanh(a1 @ Ww1^T) [4096,64]; ew = exp(-exp(wd @ Ww2^T + bw2))
    sgemm_kernel<<<dim3(1, 32), blk256>>>(a1, HH, Ww1, HH, wd, GRR,
                                          MT, GRR, HH, nullptr, 1, 0, nullptr);
    sgemm_kernel<<<dim3(4, 32), blk256>>>(wd, GRR, Ww2, GRR, ewb, KD,
                                          MT, KD, GRR, bw2, 0, 2, nullptr);

    // 5. bonus scalar
    c_kernel<<<MT, 128>>>(rb, kb, bonus, cb);

    // 6. recurrence
    recur_kernel<<<32, blk256>>>(rb, kb, ewb, vb, cb, ob);

    // 7. LayerNorm + swish gate
    ln_kernel<<<MT * NHH, blk256>>>(ob, gb, ln_w, ln_b, ogb);

    // 8. output projection
    sgemm_kernel<<<dim3(8, 32), blk256>>>(ogb, VD, Wo, VD, out, HH,
                                          MT, HH, VD, nullptr, 0, 0, nullptr);
}

// round 6
// speedup vs baseline: 1.4452x; 1.4452x over previous
#include <cuda_runtime.h>
#include <cstdint>

// Problem constants
#define BB   2
#define LL   2048
#define HH   1024
#define NHH  4
#define KD   512
#define VD   1024
#define DKK  128
#define DVV  256
#define PRR  32
#define GRR  64
#define MT   4096   // total tokens B*L

// ---------------- scratch (static __device__, no allocation) ----------------
__device__ float g_ax[MT * HH];          // lerped x with mu_x
__device__ float g_xp[MT * 160];         // tanh proj, 5*PR
__device__ float g_amix[5][MT * HH];     // lerped inputs for r,w,k,v,g
__device__ float g_r [MT * KD];
__device__ float g_k [MT * KD];
__device__ float g_v [MT * VD];
__device__ float g_g [MT * VD];
__device__ float g_wd[MT * GRR];
__device__ float g_ew[MT * KD];          // exp(-exp(w_raw))
__device__ float g_c [MT * NHH];         // bonus scalar per (token, head)
__device__ float g_o [MT * VD];          // recurrence output
__device__ float g_og[MT * VD];          // after LN + gate

// ---------------- elementwise: ax = x + (xprev - x)*mu_x ----------------
__global__ void ax_kernel(const float* __restrict__ x,
                          const float* __restrict__ mu_x,
                          float* __restrict__ ax) {
    size_t i = (size_t)blockIdx.x * blockDim.x + threadIdx.x;
    if (i >= (size_t)MT * HH) return;
    int n = (int)(i & (HH - 1));
    size_t m = i >> 10;
    float mu = mu_x[n];
    float xv = x[i];
    float xp = ((m & (LL - 1)) == 0) ? 0.f : x[i - HH];
    ax[i] = xv + (xp - xv) * mu;
}

// ---------------- tf32 tensor-core GEMM ------------------------------------
// C = epi(act(A @ W^T + bias)).  A:[M,K] K-contig, W:[N,K] K-contig.
// CTA tile 128x128, BK=16, 8 warps of 64x32. mma.sync.m16n8k8 tf32.
// epi: 0 = store, 1 = lerp-with-x, 2 = exp(-exp(val)). act: tanh if 1.
// blockIdx.z multiplexes independent GEMMs via the z-strides.
__device__ __forceinline__ uint32_t f2tf32(float v) {
    uint32_t t;
    asm("cvt.rna.tf32.f32 %0, %1;" : "=r"(t) : "f"(v));
    return t;
}

__global__ __launch_bounds__(256, 2)
void tgemm_kernel(const float* __restrict__ A0, int lda, long zAs,
                  const float* __restrict__ W0, int ldw, long zWs,
                  float* __restrict__ C0, int ldc, long zCs,
                  int M, int N, int Kdim,
                  const float* __restrict__ bias0, long zBs,
                  int act, int epi,
                  const float* __restrict__ xsrc) {
    const float* A = A0 + (long)blockIdx.z * zAs;
    const float* W = W0 + (long)blockIdx.z * zWs;
    float* C = C0 + (long)blockIdx.z * zCs;
    const float* bias = bias0 ? (bias0 + (long)blockIdx.z * zBs) : nullptr;

    __shared__ float As[2][128][20];   // [m][k], stride 20 -> conflict-free frags
    __shared__ float Bs[2][128][20];   // [n][k]

    int tid = threadIdx.x;
    int mBase = blockIdx.y * 128;
    int nBase = blockIdx.x * 128;
    int lr = tid >> 1;            // 0..127 (row for staging)
    int lc = (tid & 1) * 8;       // 0 or 8 (k-offset for staging)
    int w = tid >> 5, lane = tid & 31;
    int wm = (w >> 2) * 64;       // warp m-offset (0/64)
    int wn = (w & 3) * 32;        // warp n-offset (0/32/64/96)
    int grp = lane >> 2, tig = lane & 3;

    float acc[4][4][4];
#pragma unroll
    for (int mi = 0; mi < 4; mi++)
#pragma unroll
        for (int ni = 0; ni < 4; ni++)
#pragma unroll
            for (int q = 0; q < 4; q++) acc[mi][ni][q] = 0.f;

    int nt = Kdim >> 4;
    int nrow = nBase + lr;
    const float* apBase = A + (size_t)(mBase + lr) * lda + lc;
    const float* wpBase = W + (size_t)nrow * ldw + lc;

    float av[8], bv[8];
    // prologue: tile 0
    {
        const float* ap = apBase;
        *(float4*)(av)     = *(const float4*)(ap);
        *(float4*)(av + 4) = *(const float4*)(ap + 4);
        if (nrow < N) {
            *(float4*)(bv)     = *(const float4*)(wpBase);
            *(float4*)(bv + 4) = *(const float4*)(wpBase + 4);
        } else {
#pragma unroll
            for (int j = 0; j < 8; j++) bv[j] = 0.f;
        }
#pragma unroll
        for (int j = 0; j < 8; j++) {
            As[0][lr][lc + j] = __uint_as_float(f2tf32(av[j]));
            Bs[0][lr][lc + j] = __uint_as_float(f2tf32(bv[j]));
        }
    }
    __syncthreads();

    for (int kt = 0; kt < nt; kt++) {
        int cur = kt & 1;
        bool more = (kt + 1 < nt);
        if (more) {
            const float* ap = apBase + (kt + 1) * 16;
            *(float4*)(av)     = *(const float4*)(ap);
            *(float4*)(av + 4) = *(const float4*)(ap + 4);
            if (nrow < N) {
                const float* wp = wpBase + (kt + 1) * 16;
                *(float4*)(bv)     = *(const float4*)(wp);
                *(float4*)(bv + 4) = *(const float4*)(wp + 4);
            }
        }
#pragma unroll
        for (int k0 = 0; k0 < 16; k0 += 8) {
            uint32_t af[4][4], bf[4][2];
#pragma unroll
            for (int mi = 0; mi < 4; mi++) {
                int r0 = wm + mi * 16 + grp;
                af[mi][0] = __float_as_uint(As[cur][r0][k0 + tig]);
                af[mi][1] = __float_as_uint(As[cur][r0 + 8][k0 + tig]);
                af[mi][2] = __float_as_uint(As[cur][r0][k0 + tig + 4]);
                af[mi][3] = __float_as_uint(As[cur][r0 + 8][k0 + tig + 4]);
            }
#pragma unroll
            for (int ni = 0; ni < 4; ni++) {
                int c0 = wn + ni * 8 + grp;
                bf[ni][0] = __float_as_uint(Bs[cur][c0][k0 + tig]);
                bf[ni][1] = __float_as_uint(Bs[cur][c0][k0 + tig + 4]);
            }
#pragma unroll
            for (int mi = 0; mi < 4; mi++)
#pragma unroll
                for (int ni = 0; ni < 4; ni++) {
                    asm volatile(
                        "mma.sync.aligned.m16n8k8.row.col.f32.tf32.tf32.f32 "
                        "{%0,%1,%2,%3}, {%4,%5,%6,%7}, {%8,%9}, {%0,%1,%2,%3};"
                        : "+f"(acc[mi][ni][0]), "+f"(acc[mi][ni][1]),
                          "+f"(acc[mi][ni][2]), "+f"(acc[mi][ni][3])
                        : "r"(af[mi][0]), "r"(af[mi][1]),
                          "r"(af[mi][2]), "r"(af[mi][3]),
                          "r"(bf[ni][0]), "r"(bf[ni][1]));
                }
        }
        if (more) {
            int nxt = cur ^ 1;
#pragma unroll
            for (int j = 0; j < 8; j++) {
                As[nxt][lr][lc + j] = __uint_as_float(f2tf32(av[j]));
                Bs[nxt][lr][lc + j] = __uint_as_float(f2tf32(bv[j]));
            }
        }
        __syncthreads();
    }

    // epilogue
#pragma unroll
    for (int mi = 0; mi < 4; mi++) {
#pragma unroll
        for (int ni = 0; ni < 4; ni++) {
#pragma unroll
            for (int q = 0; q < 4; q++) {
                int m = mBase + wm + mi * 16 + grp + ((q & 2) ? 8 : 0);
                int n = nBase + wn + ni * 8 + tig * 2 + (q & 1);
                if (n >= N) continue;
                float v = acc[mi][ni][q];
                if (bias) v += bias[n];
                if (act) v = tanhf(v);
                if (epi == 1) {
                    float xv = xsrc[(size_t)m * HH + n];
                    float xp = ((m & (LL - 1)) == 0) ? 0.f
                               : xsrc[(size_t)(m - 1) * HH + n];
                    v = xv + (xp - xv) * v;
                } else if (epi == 2) {
                    v = expf(-expf(v));
                }
                C[(size_t)m * ldc + n] = v;
            }
        }
    }
}

// ---------------- per-(token,head) bonus scalar c = sum r*bonus*k ----------
__global__ void c_kernel(const float* __restrict__ r,
                         const float* __restrict__ kk,
                         const float* __restrict__ bonus,
                         float* __restrict__ c) {
    int t = blockIdx.x;
    int h = threadIdx.x >> 5, lane = threadIdx.x & 31;
    const float* rp = r  + (size_t)t * KD + h * DKK;
    const float* kp = kk + (size_t)t * KD + h * DKK;
    const float* bp = bonus + h * DKK;
    float s = 0.f;
#pragma unroll
    for (int j = lane; j < DKK; j += 32) s += rp[j] * bp[j] * kp[j];
#pragma unroll
    for (int o = 16; o; o >>= 1) s += __shfl_xor_sync(0xffffffffu, s, o);
    if (!lane) c[(size_t)t * NHH + h] = s;
}

// ---------------- sequential recurrence (software-pipelined) -------------
#define OFF_R 0
#define OFF_K 128
#define OFF_W 256
#define OFF_V 384
#define OFF_C 448
__global__ __launch_bounds__(256)
void recur_kernel(const float* __restrict__ r,
                  const float* __restrict__ kk,
                  const float* __restrict__ ew,
                  const float* __restrict__ v,
                  const float* __restrict__ c,
                  float* __restrict__ o) {
    int blk = blockIdx.x;
    int chain = blk >> 2;
    int vb = blk & 3;
    int b = chain >> 2, h = chain & 3;
    int tid = threadIdx.x;
    int kg = tid >> 6;
    int vi = tid & 63;

    __shared__ float buf[2][DKK * 3 + 65];
    __shared__ float part[4][64];

    float S[32];
#pragma unroll
    for (int j = 0; j < 32; j++) S[j] = 0.f;

    size_t tbase = (size_t)b * LL;

    float ar = 0.f, ak = 0.f, aw = 0.f, av = 0.f, ac = 0.f;
    {
        size_t tok = tbase;
        if (tid < DKK) {
            ar = r [tok * KD + h * DKK + tid];
            ak = kk[tok * KD + h * DKK + tid];
            aw = ew[tok * KD + h * DKK + tid];
        } else if (tid < DKK + 64) {
            av = v[tok * VD + h * DVV + vb * 64 + (tid - DKK)];
        } else if (tid == DKK + 64) {
            ac = c[tok * NHH + h];
        }
        float* Bn = buf[0];
        if (tid < DKK) {
            Bn[OFF_R + tid] = ar;
            Bn[OFF_K + tid] = ak;
            Bn[OFF_W + tid] = aw;
        } else if (tid < DKK + 64) {
            Bn[OFF_V + (tid - DKK)] = av;
        } else if (tid == DKK + 64) {
            Bn[OFF_C] = ac;
        }
    }
    __syncthreads();

    int pcur = 0;
    for (int t = 0; t < LL; t++) {
        if (t + 1 < LL) {
            size_t tok = tbase + t + 1;
            if (tid < DKK) {
                ar = r [tok * KD + h * DKK + tid];
                ak = kk[tok * KD + h * DKK + tid];
                aw = ew[tok * KD + h * DKK + tid];
            } else if (tid < DKK + 64) {
                av = v[tok * VD + h * DVV + vb * 64 + (tid - DKK)];
            } else if (tid == DKK + 64) {
                ac = c[tok * NHH + h];
            }
        }

        const float* Bc = buf[pcur];
        float p = 0.f;
#pragma unroll
        for (int j = 0; j < 32; j++) p += Bc[OFF_R + kg * 32 + j] * S[j];
        part[kg][vi] = p;
        __syncthreads();

        if (tid < 64) {
            float cv = Bc[OFF_C];
            float ov = part[0][tid] + part[1][tid] + part[2][tid] + part[3][tid]
                     + cv * Bc[OFF_V + tid];
            o[(tbase + t) * VD + h * DVV + vb * 64 + tid] = ov;
        }
        float vv = Bc[OFF_V + vi];
#pragma unroll
        for (int j = 0; j < 32; j++) {
            S[j] = Bc[OFF_W + kg * 32 + j] * S[j] + Bc[OFF_K + kg * 32 + j] * vv;
        }

        if (t + 1 < LL) {
            float* Bn = buf[pcur ^ 1];
            if (tid < DKK) {
                Bn[OFF_R + tid] = ar;
                Bn[OFF_K + tid] = ak;
                Bn[OFF_W + tid] = aw;
            } else if (tid < DKK + 64) {
                Bn[OFF_V + (tid - DKK)] = av;
            } else if (tid == DKK + 64) {
                Bn[OFF_C] = ac;
            }
        }
        __syncthreads();
        pcur ^= 1;
    }
}

// ---------------- per-head LayerNorm + swish gate -----------------------
__global__ __launch_bounds__(256)
void ln_kernel(const float* __restrict__ o,
               const float* __restrict__ g,
               const float* __restrict__ ln_w,
               const float* __restrict__ ln_b,
               float* __restrict__ og) {
    int th = blockIdx.x;
    int t = th >> 2, h = th & 3;
    int vv = threadIdx.x;
    size_t idx = (size_t)t * VD + h * DVV + vv;
    float val = o[idx];

    __shared__ float rs[8], rs2[8];
    float s1 = val, s2 = val * val;
#pragma unroll
    for (int off = 16; off; off >>= 1) {
        s1 += __shfl_xor_sync(0xffffffffu, s1, off);
        s2 += __shfl_xor_sync(0xffffffffu, s2, off);
    }
    int warp = vv >> 5, lane = vv & 31;
    if (!lane) { rs[warp] = s1; rs2[warp] = s2; }
    __syncthreads();
    float tot = 0.f, tot2 = 0.f;
#pragma unroll
    for (int i = 0; i < 8; i++) { tot += rs[i]; tot2 += rs2[i]; }
    float mean = tot * (1.f / DVV);
    float var = tot2 * (1.f / DVV) - mean * mean;
    float inv = rsqrtf(var + 1e-5f);
    float on = (val - mean) * inv * ln_w[vv] + ln_b[vv];
    float gv = g[idx];
    og[idx] = on * gv * (1.f / (1.f + expf(-gv)));
}

// ---------------- host launcher -----------------------------------------
static float* sym(const void* s) {
    void* p = nullptr;
    cudaGetSymbolAddress(&p, s);
    return (float*)p;
}

extern "C" void kernel_launch(void* const* d_in, const int* in_sizes, int n_in,
                              void* d_out, int out_size) {
    const float* x      = (const float*)d_in[0];
    const float* mu_x   = (const float*)d_in[1];
    const float* Wx1    = (const float*)d_in[2];   // [160,1024]
    const float* Wx2    = (const float*)d_in[3];   // [1024,160]
    const float* x_bias = (const float*)d_in[4];   // [5,1024]
    const float* Wr     = (const float*)d_in[5];   // [512,1024]
    const float* Wk     = (const float*)d_in[6];
    const float* Wv     = (const float*)d_in[7];   // [1024,1024]
    const float* Wg     = (const float*)d_in[8];
    const float* Ww1    = (const float*)d_in[9];   // [64,1024]
    const float* Ww2    = (const float*)d_in[10];  // [512,64]
    const float* bw2    = (const float*)d_in[11];  // [512]
    const float* bonus  = (const float*)d_in[12];  // [4,128]
    const float* ln_w   = (const float*)d_in[13];
    const float* ln_b   = (const float*)d_in[14];
    const float* Wo     = (const float*)d_in[15];  // [1024,1024]
    float* out = (float*)d_out;

    float* ax = sym(g_ax); float* xp = sym(g_xp);
    float* am = sym(g_amix);
    float* rb = sym(g_r);  float* kb = sym(g_k);
    float* vb = sym(g_v);  float* gb = sym(g_g);
    float* wd = sym(g_wd); float* ewb = sym(g_ew);
    float* cb = sym(g_c);  float* ob = sym(g_o); float* ogb = sym(g_og);

    dim3 blk256(256);

    // 1. token-shift lerp with mu_x
    ax_kernel<<<(MT * HH + 255) / 256, blk256>>>(x, mu_x, ax);

    // 2. xp = tanh(ax @ Wx1^T)   [4096,160]
    tgemm_kernel<<<dim3(2, 32, 1), blk256>>>(ax, HH, 0, Wx1, HH, 0,
                                             xp, 160, 0,
                                             MT, 160, HH, nullptr, 0, 1, 0, nullptr);

    // 3. fused 5 mixing GEMMs (blockIdx.z): a_z = x + (xprev-x)*(xp_z@Wx2_z^T + b_z)
    tgemm_kernel<<<dim3(8, 32, 5), blk256>>>(xp, 160, PRR,
                                             Wx2, 160, PRR,
                                             am, HH, (long)MT * HH,
                                             MT, HH, PRR,
                                             x_bias, HH, 0, 1, x);

    // 4. projections
    tgemm_kernel<<<dim3(4, 32, 1), blk256>>>(am + 0L * MT * HH, HH, 0, Wr, HH, 0,
                                             rb, KD, 0, MT, KD, HH,
                                             nullptr, 0, 0, 0, nullptr);
    tgemm_kernel<<<dim3(4, 32, 1), blk256>>>(am + 2L * MT * HH, HH, 0, Wk, HH, 0,
                                             kb, KD, 0, MT, KD, HH,
                                             nullptr, 0, 0, 0, nullptr);
    tgemm_kernel<<<dim3(8, 32, 1), blk256>>>(am + 3L * MT * HH, HH, 0, Wv, HH, 0,
                                             vb, VD, 0, MT, VD, HH,
                                             nullptr, 0, 0, 0, nullptr);
    tgemm_kernel<<<dim3(8, 32, 1), blk256>>>(am + 4L * MT * HH, HH, 0, Wg, HH, 0,
                                             gb, VD, 0, MT, VD, HH,
                                             nullptr, 0, 0, 0, nullptr);
    // w LoRA: wd = tanh(a1 @ Ww1^T); ew = exp(-exp(wd @ Ww2^T + bw2))
    tgemm_kernel<<<dim3(1, 32, 1), blk256>>>(am + 1L * MT * HH, HH, 0, Ww1, HH, 0,
                                             wd, GRR, 0, MT, GRR, HH,
                                             nullptr, 0, 1, 0, nullptr);
    tgemm_kernel<<<dim3(4, 32, 1), blk256>>>(wd, GRR, 0, Ww2, GRR, 0,
                                             ewb, KD, 0, MT, KD, GRR,
                                             bw2, 0, 0, 2, nullptr);

    // 5. bonus scalar
    c_kernel<<<MT, 128>>>(rb, kb, bonus, cb);

    // 6. recurrence
    recur_kernel<<<32, blk256>>>(rb, kb, ewb, vb, cb, ob);

    // 7. LayerNorm + swish gate
    ln_kernel<<<MT * NHH, blk256>>>(ob, gb, ln_w, ln_b, ogb);

    // 8. output projection
    tgemm_kernel<<<dim3(8, 32, 1), blk256>>>(ogb, VD, 0, Wo, VD, 0,
                                             out, HH, 0, MT, HH, VD,
                                             nullptr, 0, 0, 0, nullptr);
}

// round 7
// speedup vs baseline: 1.7516x; 1.2120x over previous
#include <cuda_runtime.h>
#include <cstdint>

// Problem constants
#define BB   2
#define LL   2048
#define HH   1024
#define NHH  4
#define KD   512
#define VD   1024
#define DKK  128
#define DVV  256
#define PRR  32
#define GRR  64
#define MT   4096   // total tokens B*L

// ---------------- scratch (static __device__, no allocation) ----------------
__device__ float g_ax[MT * HH];          // lerped x with mu_x
__device__ float g_xp[MT * 160];         // tanh proj, 5*PR
__device__ float g_amix[5][MT * HH];     // lerped inputs for r,w,k,v,g
__device__ float g_r [MT * KD];
__device__ float g_k [MT * KD];
__device__ float g_v [MT * VD];
__device__ float g_g [MT * VD];
__device__ float g_wd[MT * GRR];
__device__ float g_ew[MT * KD];          // exp(-exp(w_raw))
__device__ float g_c [MT * NHH];         // bonus scalar per (token, head)
__device__ float g_o [MT * VD];          // recurrence output
__device__ float g_og[MT * VD];          // after LN + gate

// ---------------- elementwise: ax = x + (xprev - x)*mu_x ----------------
__global__ void ax_kernel(const float* __restrict__ x,
                          const float* __restrict__ mu_x,
                          float* __restrict__ ax) {
    size_t i = (size_t)blockIdx.x * blockDim.x + threadIdx.x;
    if (i >= (size_t)MT * HH) return;
    int n = (int)(i & (HH - 1));
    size_t m = i >> 10;
    float mu = mu_x[n];
    float xv = x[i];
    float xp = ((m & (LL - 1)) == 0) ? 0.f : x[i - HH];
    ax[i] = xv + (xp - xv) * mu;
}

// ---------------- tf32 tensor-core GEMM ------------------------------------
// C = epi(act(A @ W^T + bias)).  A:[M,K] K-contig, W:[N,K] K-contig.
// CTA tile 128x128, BK=16, 8 warps of 64x32. mma.sync.m16n8k8 tf32.
// Per-z descriptors allow fusing independent GEMMs of identical shape.
struct GemmZ  { const float* A; const float* W; float* C; const float* bias; };
struct GemmZ5 { GemmZ z[5]; };

__device__ __forceinline__ uint32_t f2tf32(float v) {
    uint32_t t;
    asm("cvt.rna.tf32.f32 %0, %1;" : "=r"(t) : "f"(v));
    return t;
}

__global__ __launch_bounds__(256, 2)
void tgemm_kernel(GemmZ5 dz, int lda, int ldw, int ldc,
                  int M, int N, int Kdim,
                  int act, int epi,
                  const float* __restrict__ xsrc) {
    const GemmZ gd = dz.z[blockIdx.z];
    const float* A = gd.A;
    const float* W = gd.W;
    float* C = gd.C;
    const float* bias = gd.bias;

    __shared__ float As[2][128][20];   // [m][k], stride 20 -> conflict-free frags
    __shared__ float Bs[2][128][20];   // [n][k]

    int tid = threadIdx.x;
    int mBase = blockIdx.y * 128;
    int nBase = blockIdx.x * 128;
    int lr = tid >> 1;            // 0..127 (row for staging)
    int lc = (tid & 1) * 8;       // 0 or 8 (k-offset for staging)
    int w = tid >> 5, lane = tid & 31;
    int wm = (w >> 2) * 64;       // warp m-offset (0/64)
    int wn = (w & 3) * 32;        // warp n-offset (0/32/64/96)
    int grp = lane >> 2, tig = lane & 3;

    float acc[4][4][4];
#pragma unroll
    for (int mi = 0; mi < 4; mi++)
#pragma unroll
        for (int ni = 0; ni < 4; ni++)
#pragma unroll
            for (int q = 0; q < 4; q++) acc[mi][ni][q] = 0.f;

    int nt = Kdim >> 4;
    int nrow = nBase + lr;
    const float* apBase = A + (size_t)(mBase + lr) * lda + lc;
    const float* wpBase = W + (size_t)nrow * ldw + lc;

    float av[8], bv[8];
    // prologue: tile 0
    {
        const float* ap = apBase;
        *(float4*)(av)     = *(const float4*)(ap);
        *(float4*)(av + 4) = *(const float4*)(ap + 4);
        if (nrow < N) {
            *(float4*)(bv)     = *(const float4*)(wpBase);
            *(float4*)(bv + 4) = *(const float4*)(wpBase + 4);
        } else {
#pragma unroll
            for (int j = 0; j < 8; j++) bv[j] = 0.f;
        }
#pragma unroll
        for (int j = 0; j < 8; j++) {
            As[0][lr][lc + j] = __uint_as_float(f2tf32(av[j]));
            Bs[0][lr][lc + j] = __uint_as_float(f2tf32(bv[j]));
        }
    }
    __syncthreads();

    for (int kt = 0; kt < nt; kt++) {
        int cur = kt & 1;
        bool more = (kt + 1 < nt);
        if (more) {
            const float* ap = apBase + (kt + 1) * 16;
            *(float4*)(av)     = *(const float4*)(ap);
            *(float4*)(av + 4) = *(const float4*)(ap + 4);
            if (nrow < N) {
                const float* wp = wpBase + (kt + 1) * 16;
                *(float4*)(bv)     = *(const float4*)(wp);
                *(float4*)(bv + 4) = *(const float4*)(wp + 4);
            }
        }
#pragma unroll
        for (int k0 = 0; k0 < 16; k0 += 8) {
            uint32_t af[4][4], bf[4][2];
#pragma unroll
            for (int mi = 0; mi < 4; mi++) {
                int r0 = wm + mi * 16 + grp;
                af[mi][0] = __float_as_uint(As[cur][r0][k0 + tig]);
                af[mi][1] = __float_as_uint(As[cur][r0 + 8][k0 + tig]);
                af[mi][2] = __float_as_uint(As[cur][r0][k0 + tig + 4]);
                af[mi][3] = __float_as_uint(As[cur][r0 + 8][k0 + tig + 4]);
            }
#pragma unroll
            for (int ni = 0; ni < 4; ni++) {
                int c0 = wn + ni * 8 + grp;
                bf[ni][0] = __float_as_uint(Bs[cur][c0][k0 + tig]);
                bf[ni][1] = __float_as_uint(Bs[cur][c0][k0 + tig + 4]);
            }
#pragma unroll
            for (int mi = 0; mi < 4; mi++)
#pragma unroll
                for (int ni = 0; ni < 4; ni++) {
                    asm volatile(
                        "mma.sync.aligned.m16n8k8.row.col.f32.tf32.tf32.f32 "
                        "{%0,%1,%2,%3}, {%4,%5,%6,%7}, {%8,%9}, {%0,%1,%2,%3};"
                        : "+f"(acc[mi][ni][0]), "+f"(acc[mi][ni][1]),
                          "+f"(acc[mi][ni][2]), "+f"(acc[mi][ni][3])
                        : "r"(af[mi][0]), "r"(af[mi][1]),
                          "r"(af[mi][2]), "r"(af[mi][3]),
                          "r"(bf[ni][0]), "r"(bf[ni][1]));
                }
        }
        if (more) {
            int nxt = cur ^ 1;
#pragma unroll
            for (int j = 0; j < 8; j++) {
                As[nxt][lr][lc + j] = __uint_as_float(f2tf32(av[j]));
                Bs[nxt][lr][lc + j] = __uint_as_float(f2tf32(bv[j]));
            }
        }
        __syncthreads();
    }

    // epilogue: float2-vectorized (paired accumulator cols are adjacent n)
#pragma unroll
    for (int mi = 0; mi < 4; mi++) {
#pragma unroll
        for (int ni = 0; ni < 4; ni++) {
            int m0 = mBase + wm + mi * 16 + grp;
            int n0 = nBase + wn + ni * 8 + tig * 2;
            if (n0 >= N) continue;
#pragma unroll
            for (int hr = 0; hr < 2; hr++) {
                int m = m0 + hr * 8;
                float vx = acc[mi][ni][hr * 2 + 0];
                float vy = acc[mi][ni][hr * 2 + 1];
                if (bias) { vx += bias[n0]; vy += bias[n0 + 1]; }
                if (act)  { vx = tanhf(vx); vy = tanhf(vy); }
                if (epi == 1) {
                    float2 xv = *(const float2*)&xsrc[(size_t)m * HH + n0];
                    float2 xp = ((m & (LL - 1)) == 0) ? make_float2(0.f, 0.f)
                              : *(const float2*)&xsrc[(size_t)(m - 1) * HH + n0];
                    vx = xv.x + (xp.x - xv.x) * vx;
                    vy = xv.y + (xp.y - xv.y) * vy;
                } else if (epi == 2) {
                    vx = expf(-expf(vx));
                    vy = expf(-expf(vy));
                }
                *(float2*)&C[(size_t)m * ldc + n0] = make_float2(vx, vy);
            }
        }
    }
}

// ---------------- per-(token,head) bonus scalar c = sum r*bonus*k ----------
__global__ void c_kernel(const float* __restrict__ r,
                         const float* __restrict__ kk,
                         const float* __restrict__ bonus,
                         float* __restrict__ c) {
    int t = blockIdx.x;
    int h = threadIdx.x >> 5, lane = threadIdx.x & 31;
    const float* rp = r  + (size_t)t * KD + h * DKK;
    const float* kp = kk + (size_t)t * KD + h * DKK;
    const float* bp = bonus + h * DKK;
    float s = 0.f;
#pragma unroll
    for (int j = lane; j < DKK; j += 32) s += rp[j] * bp[j] * kp[j];
#pragma unroll
    for (int o = 16; o; o >>= 1) s += __shfl_xor_sync(0xffffffffu, s, o);
    if (!lane) c[(size_t)t * NHH + h] = s;
}

// ---------------- sequential recurrence (128 CTAs, software-pipelined) ----
// 128 CTAs: 16 per chain (chain = b*NH+h), each CTA covers 16 v-columns.
// Thread layout: kg = tid/16 (8 k each), vi = tid%16. State S[8] in regs.
#define OFF_R 0
#define OFF_K 128
#define OFF_W 256
#define OFF_V 384
#define OFF_C 400
__global__ __launch_bounds__(256)
void recur_kernel(const float* __restrict__ r,
                  const float* __restrict__ kk,
                  const float* __restrict__ ew,
                  const float* __restrict__ v,
                  const float* __restrict__ c,
                  float* __restrict__ o) {
    int blk = blockIdx.x;
    int chain = blk >> 4;       // 0..7
    int vb = blk & 15;          // 16-col block
    int b = chain >> 2, h = chain & 3;
    int tid = threadIdx.x;
    int kg = tid >> 4;          // 0..15, owns k-range kg*8..kg*8+7
    int vi = tid & 15;          // v column within block

    __shared__ float buf[2][3 * DKK + 17];
    __shared__ float part[256];  // [kg*16 + vi] -> conflict-free

    float S[8];
#pragma unroll
    for (int j = 0; j < 8; j++) S[j] = 0.f;

    size_t tbase = (size_t)b * LL;

    float ar = 0.f, ak = 0.f, aw = 0.f, av = 0.f, ac = 0.f;
    // prologue: load token 0
    {
        size_t tok = tbase;
        if (tid < DKK) {
            ar = r [tok * KD + h * DKK + tid];
            ak = kk[tok * KD + h * DKK + tid];
            aw = ew[tok * KD + h * DKK + tid];
        } else if (tid < DKK + 16) {
            av = v[tok * VD + h * DVV + vb * 16 + (tid - DKK)];
        } else if (tid == DKK + 16) {
            ac = c[tok * NHH + h];
        }
        float* Bn = buf[0];
        if (tid < DKK) {
            Bn[OFF_R + tid] = ar;
            Bn[OFF_K + tid] = ak;
            Bn[OFF_W + tid] = aw;
        } else if (tid < DKK + 16) {
            Bn[OFF_V + (tid - DKK)] = av;
        } else if (tid == DKK + 16) {
            Bn[OFF_C] = ac;
        }
    }
    __syncthreads();

    int pcur = 0;
    for (int t = 0; t < LL; t++) {
        // prefetch token t+1 into registers (overlaps with compute)
        if (t + 1 < LL) {
            size_t tok = tbase + t + 1;
            if (tid < DKK) {
                ar = r [tok * KD + h * DKK + tid];
                ak = kk[tok * KD + h * DKK + tid];
                aw = ew[tok * KD + h * DKK + tid];
            } else if (tid < DKK + 16) {
                av = v[tok * VD + h * DVV + vb * 16 + (tid - DKK)];
            } else if (tid == DKK + 16) {
                ac = c[tok * NHH + h];
            }
        }

        const float* Bc = buf[pcur];
        // o partial over this thread's 8-k slice
        float p = 0.f;
#pragma unroll
        for (int j = 0; j < 8; j++) p += Bc[OFF_R + kg * 8 + j] * S[j];
        part[kg * 16 + vi] = p;
        __syncthreads();

        if (tid < 16) {
            float s = 0.f;
#pragma unroll
            for (int g = 0; g < 16; g++) s += part[g * 16 + tid];
            s += Bc[OFF_C] * Bc[OFF_V + tid];
            o[(tbase + t) * VD + h * DVV + vb * 16 + tid] = s;
        }
        // state update: S = ew*S + k*v
        float vv = Bc[OFF_V + vi];
#pragma unroll
        for (int j = 0; j < 8; j++) {
            S[j] = Bc[OFF_W + kg * 8 + j] * S[j] + Bc[OFF_K + kg * 8 + j] * vv;
        }

        // stage prefetched token into the other buffer
        if (t + 1 < LL) {
            float* Bn = buf[pcur ^ 1];
            if (tid < DKK) {
                Bn[OFF_R + tid] = ar;
                Bn[OFF_K + tid] = ak;
                Bn[OFF_W + tid] = aw;
            } else if (tid < DKK + 16) {
                Bn[OFF_V + (tid - DKK)] = av;
            } else if (tid == DKK + 16) {
                Bn[OFF_C] = ac;
            }
        }
        __syncthreads();
        pcur ^= 1;
    }
}

// ---------------- per-head LayerNorm + swish gate -----------------------
__global__ __launch_bounds__(256)
void ln_kernel(const float* __restrict__ o,
               const float* __restrict__ g,
               const float* __restrict__ ln_w,
               const float* __restrict__ ln_b,
               float* __restrict__ og) {
    int th = blockIdx.x;
    int t = th >> 2, h = th & 3;
    int vv = threadIdx.x;
    size_t idx = (size_t)t * VD + h * DVV + vv;
    float val = o[idx];

    __shared__ float rs[8], rs2[8];
    float s1 = val, s2 = val * val;
#pragma unroll
    for (int off = 16; off; off >>= 1) {
        s1 += __shfl_xor_sync(0xffffffffu, s1, off);
        s2 += __shfl_xor_sync(0xffffffffu, s2, off);
    }
    int warp = vv >> 5, lane = vv & 31;
    if (!lane) { rs[warp] = s1; rs2[warp] = s2; }
    __syncthreads();
    float tot = 0.f, tot2 = 0.f;
#pragma unroll
    for (int i = 0; i < 8; i++) { tot += rs[i]; tot2 += rs2[i]; }
    float mean = tot * (1.f / DVV);
    float var = tot2 * (1.f / DVV) - mean * mean;
    float inv = rsqrtf(var + 1e-5f);
    float on = (val - mean) * inv * ln_w[vv] + ln_b[vv];
    float gv = g[idx];
    og[idx] = on * gv * (1.f / (1.f + expf(-gv)));
}

// ---------------- host launcher -----------------------------------------
static float* sym(const void* s) {
    void* p = nullptr;
    cudaGetSymbolAddress(&p, s);
    return (float*)p;
}

static GemmZ5 mk1(const float* A, const float* W, float* C, const float* bias) {
    GemmZ5 d{};
    d.z[0] = GemmZ{A, W, C, bias};
    return d;
}

extern "C" void kernel_launch(void* const* d_in, const int* in_sizes, int n_in,
                              void* d_out, int out_size) {
    const float* x      = (const float*)d_in[0];
    const float* mu_x   = (const float*)d_in[1];
    const float* Wx1    = (const float*)d_in[2];   // [160,1024]
    const float* Wx2    = (const float*)d_in[3];   // [1024,160]
    const float* x_bias = (const float*)d_in[4];   // [5,1024]
    const float* Wr     = (const float*)d_in[5];   // [512,1024]
    const float* Wk     = (const float*)d_in[6];
    const float* Wv     = (const float*)d_in[7];   // [1024,1024]
    const float* Wg     = (const float*)d_in[8];
    const float* Ww1    = (const float*)d_in[9];   // [64,1024]
    const float* Ww2    = (const float*)d_in[10];  // [512,64]
    const float* bw2    = (const float*)d_in[11];  // [512]
    const float* bonus  = (const float*)d_in[12];  // [4,128]
    const float* ln_w   = (const float*)d_in[13];
    const float* ln_b   = (const float*)d_in[14];
    const float* Wo     = (const float*)d_in[15];  // [1024,1024]
    float* out = (float*)d_out;

    float* ax = sym(g_ax); float* xp = sym(g_xp);
    float* am = sym(g_amix);
    float* rb = sym(g_r);  float* kb = sym(g_k);
    float* vb = sym(g_v);  float* gb = sym(g_g);
    float* wd = sym(g_wd); float* ewb = sym(g_ew);
    float* cb = sym(g_c);  float* ob = sym(g_o); float* ogb = sym(g_og);

    dim3 blk256(256);

    // 1. token-shift lerp with mu_x
    ax_kernel<<<(MT * HH + 255) / 256, blk256>>>(x, mu_x, ax);

    // 2. xp = tanh(ax @ Wx1^T)   [4096,160]
    tgemm_kernel<<<dim3(2, 32, 1), blk256>>>(mk1(ax, Wx1, xp, nullptr),
                                             HH, HH, 160, MT, 160, HH,
                                             1, 0, nullptr);

    // 3. fused 5 mixing GEMMs: a_z = x + (xprev-x)*(xp_z@Wx2_z^T + b_z)
    {
        GemmZ5 d{};
        for (int i = 0; i < 5; i++)
            d.z[i] = GemmZ{xp + i * PRR, Wx2 + i * PRR,
                           am + (long)i * MT * HH, x_bias + i * HH};
        tgemm_kernel<<<dim3(8, 32, 5), blk256>>>(d, 160, 160, HH,
                                                 MT, HH, PRR, 0, 1, x);
    }

    // 4a. fused r + k projections (z=2, 256 CTAs)
    {
        GemmZ5 d{};
        d.z[0] = GemmZ{am + 0L * MT * HH, Wr, rb, nullptr};
        d.z[1] = GemmZ{am + 2L * MT * HH, Wk, kb, nullptr};
        tgemm_kernel<<<dim3(4, 32, 2), blk256>>>(d, HH, HH, KD,
                                                 MT, KD, HH, 0, 0, nullptr);
    }
    // 4b. fused v + g projections (z=2, 512 CTAs)
    {
        GemmZ5 d{};
        d.z[0] = GemmZ{am + 3L * MT * HH, Wv, vb, nullptr};
        d.z[1] = GemmZ{am + 4L * MT * HH, Wg, gb, nullptr};
        tgemm_kernel<<<dim3(8, 32, 2), blk256>>>(d, HH, HH, VD,
                                                 MT, VD, HH, 0, 0, nullptr);
    }
    // 4c. w LoRA: wd = tanh(a1 @ Ww1^T); ew = exp(-exp(wd @ Ww2^T + bw2))
    tgemm_kernel<<<dim3(1, 32, 1), blk256>>>(mk1(am + 1L * MT * HH, Ww1, wd, nullptr),
                                             HH, HH, GRR, MT, GRR, HH,
                                             1, 0, nullptr);
    tgemm_kernel<<<dim3(4, 32, 1), blk256>>>(mk1(wd, Ww2, ewb, bw2),
                                             GRR, GRR, KD, MT, KD, GRR,
                                             0, 2, nullptr);

    // 5. bonus scalar
    c_kernel<<<MT, 128>>>(rb, kb, bonus, cb);

    // 6. recurrence (128 CTAs)
    recur_kernel<<<128, blk256>>>(rb, kb, ewb, vb, cb, ob);

    // 7. LayerNorm + swish gate
    ln_kernel<<<MT * NHH, blk256>>>(ob, gb, ln_w, ln_b, ogb);

    // 8. output projection
    tgemm_kernel<<<dim3(8, 32, 1), blk256>>>(mk1(ogb, Wo, out, nullptr),
                                             VD, VD, HH, MT, HH, VD,
                                             0, 0, nullptr);
}